// round 2
// baseline (speedup 1.0000x reference)
#include <cuda_runtime.h>

#define BB 128
#define LL 128
#define TNN 32
#define DIMM 64
#define KK4 68
#define NTHREADS 256
#define NWARPS 8

typedef unsigned long long ull;

// ---------- packed f32x2 helpers (FFMA2 path: 2 MACs/inst) ----------
__device__ __forceinline__ ull pack2(float x, float y) {
    ull r; asm("mov.b64 %0, {%1,%2};" : "=l"(r) : "f"(x), "f"(y)); return r;
}
__device__ __forceinline__ void unpack2(ull v, float& x, float& y) {
    asm("mov.b64 {%0,%1}, %2;" : "=f"(x), "=f"(y) : "l"(v));
}
__device__ __forceinline__ void fma2(ull& d, ull a, ull b) {
    asm("fma.rn.f32x2 %0, %1, %2, %0;" : "+l"(d) : "l"(a), "l"(b));
}

// ---------- shared memory layout (units: floats) ----------
#define OFF_W1   0        /* 136*128 = 17408 : pcW1 (scan) / jcW1[t]+jtW1[t] (final) */
#define OFF_W2   17408    /* 128*64  = 8192  : pcW2 (scan) / small buffers (final)  */
#define OFF_MARK 25600    /* 129*68  = 8772  */
#define OFF_WB   34372    /* 129*64  = 8256  : w / exp buffer                        */
#define OFF_LH   42628    /* 8*8*132 = 8448  : per-warp leaky(hid) tile (pad 132)    */
#define OFF_BASE 51076    /* 128 */
#define OFF_PCB1 51204    /* 128 */
#define OFF_PCB2 51332    /* 64  */
#define OFF_CV   51396    /* 68  : [relu(C[ai]) | Temb[ai]]                          */
#define OFF_SC   51464    /* 64  : condC / softmax-sum                               */
#define OFF_PMAX 51528    /* 256 */
#define OFF_PSUM 51784    /* 256 */
#define OFF_SMAX 52040    /* 64  */
#define OFF_BD   52104    /* 640 : this batch's (5,128) row                          */
#define OFF_RNZ  52744    /* 129 ints : row-nonzero flags (=!zmask)                  */
#define OFF_TLZ  52873    /* 129 ints : tail-is-zero flags                           */
#define SMEM_FLOATS 53008
#define SMEM_BYTES (SMEM_FLOATS * 4)

// 8-row x 4-col (per lane) K=68 GEMM microkernel; wgt row stride = 128 floats.
__device__ __forceinline__ void gemm8_k68(const float* __restrict__ smk,
                                          const int* roff,
                                          const float* __restrict__ wgt,
                                          int h0, ull acc[8][2]) {
#pragma unroll 2
    for (int k = 0; k < 68; k++) {
        float4 w4 = *(const float4*)(wgt + (k << 7) + h0);
        ull w01 = pack2(w4.x, w4.y), w23 = pack2(w4.z, w4.w);
#pragma unroll
        for (int q = 0; q < 8; q++) {
            float x = smk[roff[q] + k];
            ull xx = pack2(x, x);
            fma2(acc[q][0], xx, w01);
            fma2(acc[q][1], xx, w23);
        }
    }
}

__device__ __forceinline__ float leaky(float v) { return v > 0.f ? v : 0.01f * v; }

__global__ __launch_bounds__(NTHREADS, 1)
void petri_kernel(const float* __restrict__ bd,   const float* __restrict__ G,
                  const float* __restrict__ C,    const float* __restrict__ Temb,
                  const float* __restrict__ pcW1, const float* __restrict__ pcb1,
                  const float* __restrict__ pcW2, const float* __restrict__ pcb2,
                  const float* __restrict__ jcW1, const float* __restrict__ jcb1,
                  const float* __restrict__ jfW,  const float* __restrict__ jfb,
                  const float* __restrict__ jtW1, const float* __restrict__ jtb1,
                  const float* __restrict__ jtW2, const float* __restrict__ jtb2,
                  float* __restrict__ out)
{
    extern __shared__ float sm[];
    const int tid  = threadIdx.x;
    const int lane = tid & 31;
    const int w    = tid >> 5;
    const int b    = blockIdx.x;
    const int h0   = lane * 4;

    float* sW1   = sm + OFF_W1;
    float* sW2   = sm + OFF_W2;
    float* sMark = sm + OFF_MARK;
    float* sWB   = sm + OFF_WB;
    float* sLH   = sm + OFF_LH;
    float* sBase = sm + OFF_BASE;
    float* sPcb1 = sm + OFF_PCB1;
    float* sPcb2 = sm + OFF_PCB2;
    float* sCV   = sm + OFF_CV;
    float* sSC   = sm + OFF_SC;
    float* sPMAX = sm + OFF_PMAX;
    float* sPSUM = sm + OFF_PSUM;
    float* sSMAX = sm + OFF_SMAX;
    float* sBD   = sm + OFF_BD;
    int*   rownz = (int*)(sm + OFF_RNZ);
    int*   tailz = (int*)(sm + OFF_TLZ);

    // ---------------- stage weights + init state ----------------
    for (int i = tid; i < 136 * 128; i += NTHREADS) sW1[i] = pcW1[i];
    for (int i = tid; i < 128 * 64;  i += NTHREADS) sW2[i] = pcW2[i];
    if (tid < 128) sPcb1[tid] = pcb1[tid];
    if (tid < 64)  sPcb2[tid] = pcb2[tid];
    for (int i = tid; i < 640; i += NTHREADS) sBD[i] = bd[b * 640 + i];
    for (int i = tid; i < 129 * 68; i += NTHREADS) sMark[i] = 0.f;
    if (tid < 129) { rownz[tid] = 0; tailz[tid] = 1; }
    __syncthreads();
    if (tid < 64) sMark[tid] = fmaxf(G[tid], 0.f);
    __syncthreads();
    if (tid == 0) {
        int nz = 0;
        for (int j = 0; j < 68; j++) nz |= (sMark[j] != 0.f);
        rownz[0] = nz;
    }
    __syncthreads();

    float* lhw = sLH + w * (8 * 132);

    // ---------------- sequential scan over L steps ----------------
    for (int i = 0; i < LL; i++) {
        const int a = (int)sBD[i];
        if (a <= 0 || a == TNN + 1) continue;      // inactive: uniform skip
        const float tv0 = sBD[128 + i], tv1 = sBD[256 + i],
                    tv2 = sBD[384 + i], tv3 = sBD[512 + i];
        const int ai = a - 1, gi = a;
        const int nrows = i + 1;

        // Phase A: cond vector, gen row i+1 (safe: rows 0..i untouched)
        if (tid < 64)                      sCV[tid] = fmaxf(C[ai * 64 + tid], 0.f);
        else if (tid < 68)                 sCV[tid] = Temb[ai * 4 + (tid - 64)];
        else if (tid >= 128 && tid < 192)  sMark[(i + 1) * 68 + (tid - 128)] = fmaxf(G[gi * 64 + (tid - 128)], 0.f);
        else if (tid >= 192 && tid < 196) {
            float tv = (tid == 192) ? tv0 : (tid == 193) ? tv1 : (tid == 194) ? tv2 : tv3;
            sMark[(i + 1) * 68 + 64 + (tid - 192)] = tv;
        }
        if (tid == 196) tailz[i + 1] = (tv0 == 0.f && tv1 == 0.f && tv2 == 0.f && tv3 == 0.f);
        __syncthreads();

        // Phase A2: base[h] = pcb1[h] + cond @ pcW1[68:], and rownz[i+1]
        if (tid < 128) {
            float a0 = sPcb1[tid], a1 = 0.f;
#pragma unroll 4
            for (int j = 0; j < 68; j += 2) {
                a0 = fmaf(sCV[j],     sW1[(68 + j) * 128 + tid], a0);
                a1 = fmaf(sCV[j + 1], sW1[(69 + j) * 128 + tid], a1);
            }
            sBase[tid] = a0 + a1;
        }
        if (w == 6) {
            const float* row = sMark + (i + 1) * 68;
            int v = (row[lane] != 0.f) || (row[lane + 32] != 0.f);
            if (lane < 4) v |= (row[64 + lane] != 0.f);
            unsigned nz = __ballot_sync(0xffffffffu, v);
            if (lane == 0) rownz[i + 1] = (nz != 0);
        }
        __syncthreads();

        // Phase B: w = leaky(x@W1 + base) @ W2 + b2, rows 0..i, 8-row warp tiles
        for (int tile = w; tile * 8 < nrows; tile += NWARPS) {
            const int r0 = tile * 8;
            int roff[8];
#pragma unroll
            for (int q = 0; q < 8; q++) roff[q] = min(r0 + q, 128) * 68;

            ull acc[8][2];
            {
                float4 b4 = *(const float4*)(sBase + h0);
                ull b01 = pack2(b4.x, b4.y), b23 = pack2(b4.z, b4.w);
#pragma unroll
                for (int q = 0; q < 8; q++) { acc[q][0] = b01; acc[q][1] = b23; }
            }
            gemm8_k68(sMark, roff, sW1, h0, acc);

#pragma unroll
            for (int q = 0; q < 8; q++) {
                float a0, a1, a2, a3;
                unpack2(acc[q][0], a0, a1); unpack2(acc[q][1], a2, a3);
                *(float4*)(lhw + q * 132 + h0) =
                    make_float4(leaky(a0), leaky(a1), leaky(a2), leaky(a3));
            }
            __syncwarp();

            // GEMM2: half-warp per 4-row group, 4 n-cols per lane
            const int g  = lane >> 4;
            const int n0 = (lane & 15) * 4;
            const float* lhg = lhw + 4 * g * 132;
            ull acc2[4][2];
            {
                float4 b4 = *(const float4*)(sPcb2 + n0);
                ull b01 = pack2(b4.x, b4.y), b23 = pack2(b4.z, b4.w);
#pragma unroll
                for (int q = 0; q < 4; q++) { acc2[q][0] = b01; acc2[q][1] = b23; }
            }
#pragma unroll 2
            for (int h = 0; h < 128; h++) {
                float4 w4 = *(const float4*)(sW2 + (h << 6) + n0);
                ull w01 = pack2(w4.x, w4.y), w23 = pack2(w4.z, w4.w);
#pragma unroll
                for (int q = 0; q < 4; q++) {
                    float x = lhg[q * 132 + h];
                    ull xx = pack2(x, x);
                    fma2(acc2[q][0], xx, w01);
                    fma2(acc2[q][1], xx, w23);
                }
            }
#pragma unroll
            for (int q = 0; q < 4; q++) {
                int r = r0 + 4 * g + q;
                if (r < nrows) {
                    float a0, a1, a2, a3;
                    unpack2(acc2[q][0], a0, a1); unpack2(acc2[q][1], a2, a3);
                    *(float4*)(sWB + r * 64 + n0) = make_float4(a0, a1, a2, a3);
                }
            }
            __syncwarp();
        }
        __syncthreads();

        // Phase C: masked softmax over rows, per column (4 threads/column)
        {
            const int n = tid & 63, c = tid >> 6;
            float m = -1e30f;
            for (int r = c; r < nrows; r += 4) {
                float v = rownz[r] ? sWB[r * 64 + n] : -1e9f;
                m = fmaxf(m, v);
            }
            sPMAX[c * 64 + n] = m;
        }
        __syncthreads();
        if (tid < 64)
            sSMAX[tid] = fmaxf(fmaxf(sPMAX[tid], sPMAX[64 + tid]),
                               fmaxf(sPMAX[128 + tid], sPMAX[192 + tid]));
        __syncthreads();
        {
            const int n = tid & 63, c = tid >> 6;
            const float mm = sSMAX[n];
            float s = 0.f;
            for (int r = c; r < nrows; r += 4) {
                float v = rownz[r] ? sWB[r * 64 + n] : -1e9f;
                float e = expf(v - mm);
                sWB[r * 64 + n] = e;
                s += e;
            }
            sPSUM[c * 64 + n] = s;
        }
        __syncthreads();
        if (tid < 64) {
            float s = sPSUM[tid] + sPSUM[64 + tid] + sPSUM[128 + tid] + sPSUM[192 + tid];
            sSC[tid] = sCV[tid] / s;      // condC[n] / sum
        }
        __syncthreads();

        // Phase D: marking update + incremental zmask maintenance
        for (int r = w; r < nrows; r += NWARPS) {
            float e0 = sWB[r * 64 + lane];
            float e1 = sWB[r * 64 + lane + 32];
            float v0 = fmaxf(sMark[r * 68 + lane]      - e0 * sSC[lane],      0.f);
            float v1 = fmaxf(sMark[r * 68 + lane + 32] - e1 * sSC[lane + 32], 0.f);
            sMark[r * 68 + lane]      = v0;
            sMark[r * 68 + lane + 32] = v1;
            unsigned nzb = __ballot_sync(0xffffffffu, (v0 != 0.f) || (v1 != 0.f));
            if (lane == 0) rownz[r] = (nzb != 0) || (tailz[r] == 0);
        }
        __syncthreads();
    }

    // ---------------- final scoring phase (reuses W1/W2 regions) ----------------
    float* sJc  = sW1;
    float* sJt  = sW1 + 68 * 128;
    float* spool = sW2;
    float* sjcb  = sW2 + 128;
    float* sjtb  = sW2 + 256;
    float* sjw2  = sW2 + 384;
    float* sjf   = sW2 + 512;
    float* swm   = sW2 + 640;

    __syncthreads();
    if (tid < 128) sjf[tid] = jfW[tid];
    const float jfb_v = jfb[0];
    __syncthreads();

    for (int t = 0; t < TNN; t++) {
        for (int idx = tid; idx < 68 * 128; idx += NTHREADS) {
            sJc[idx] = jcW1[t * 68 * 128 + idx];
            sJt[idx] = jtW1[t * 68 * 128 + idx];
        }
        if (tid < 128) {
            sjcb[tid] = jcb1[t * 128 + tid];
            sjtb[tid] = jtb1[t * 128 + tid];
            sjw2[tid] = jtW2[t * 128 + tid];
            spool[tid] = 0.f;
        }
        __syncthreads();

        // jc path: pooled[h] = sum over nonzero rows of leaky(marking @ jcW1[t] + jcb1[t])
        float pp0 = 0.f, pp1 = 0.f, pp2 = 0.f, pp3 = 0.f;
        for (int tile = w; tile * 8 < 129; tile += NWARPS) {
            const int r0 = tile * 8;
            int roff[8];
#pragma unroll
            for (int q = 0; q < 8; q++) roff[q] = min(r0 + q, 128) * 68;
            ull acc[8][2];
            {
                float4 b4 = *(const float4*)(sjcb + h0);
                ull b01 = pack2(b4.x, b4.y), b23 = pack2(b4.z, b4.w);
#pragma unroll
                for (int q = 0; q < 8; q++) { acc[q][0] = b01; acc[q][1] = b23; }
            }
            gemm8_k68(sMark, roff, sJc, h0, acc);
#pragma unroll
            for (int q = 0; q < 8; q++) {
                int r = r0 + q;
                if (r < 129 && rownz[r]) {
                    float a0, a1, a2, a3;
                    unpack2(acc[q][0], a0, a1); unpack2(acc[q][1], a2, a3);
                    pp0 += leaky(a0); pp1 += leaky(a1);
                    pp2 += leaky(a2); pp3 += leaky(a3);
                }
            }
        }
        atomicAdd(&spool[h0 + 0], pp0);
        atomicAdd(&spool[h0 + 1], pp1);
        atomicAdd(&spool[h0 + 2], pp2);
        atomicAdd(&spool[h0 + 3], pp3);

        // jt path: tc[r] = leaky(marking @ jtW1[t] + jtb1[t]) . jtW2[t] + jtb2[t]; max over r
        const float w2a = sjw2[h0], w2b = sjw2[h0 + 1], w2c = sjw2[h0 + 2], w2d = sjw2[h0 + 3];
        const float jtb2v = jtb2[t];
        float tmax = -1e30f;
        for (int tile = w; tile * 8 < 129; tile += NWARPS) {
            const int r0 = tile * 8;
            int roff[8];
#pragma unroll
            for (int q = 0; q < 8; q++) roff[q] = min(r0 + q, 128) * 68;
            ull acc[8][2];
            {
                float4 b4 = *(const float4*)(sjtb + h0);
                ull b01 = pack2(b4.x, b4.y), b23 = pack2(b4.z, b4.w);
#pragma unroll
                for (int q = 0; q < 8; q++) { acc[q][0] = b01; acc[q][1] = b23; }
            }
            gemm8_k68(sMark, roff, sJt, h0, acc);
#pragma unroll
            for (int q = 0; q < 8; q++) {
                float a0, a1, a2, a3;
                unpack2(acc[q][0], a0, a1); unpack2(acc[q][1], a2, a3);
                float d = leaky(a0) * w2a + leaky(a1) * w2b + leaky(a2) * w2c + leaky(a3) * w2d;
                d += __shfl_xor_sync(0xffffffffu, d, 16);
                d += __shfl_xor_sync(0xffffffffu, d, 8);
                d += __shfl_xor_sync(0xffffffffu, d, 4);
                d += __shfl_xor_sync(0xffffffffu, d, 2);
                d += __shfl_xor_sync(0xffffffffu, d, 1);
                if (r0 + q < 129) tmax = fmaxf(tmax, d + jtb2v);
            }
        }
        if (lane == 0) swm[w] = tmax;
        __syncthreads();

        if (w == 0) {
            float pr = spool[lane]      * sjf[lane]
                     + spool[lane + 32] * sjf[lane + 32]
                     + spool[lane + 64] * sjf[lane + 64]
                     + spool[lane + 96] * sjf[lane + 96];
            pr += __shfl_xor_sync(0xffffffffu, pr, 16);
            pr += __shfl_xor_sync(0xffffffffu, pr, 8);
            pr += __shfl_xor_sync(0xffffffffu, pr, 4);
            pr += __shfl_xor_sync(0xffffffffu, pr, 2);
            pr += __shfl_xor_sync(0xffffffffu, pr, 1);
            if (lane == 0) {
                float res = 1.f / (1.f + expf(-(pr + jfb_v)));
                res = fmaxf(res, 1e-5f);
                float tm = swm[0];
#pragma unroll
                for (int j = 1; j < 8; j++) tm = fmaxf(tm, swm[j]);
                out[b * TNN + t] = res * tm - 0.01f * expf(res);
            }
        }
        __syncthreads();
    }
}

extern "C" void kernel_launch(void* const* d_in, const int* in_sizes, int n_in,
                              void* d_out, int out_size) {
    (void)in_sizes; (void)n_in; (void)out_size;
    cudaFuncSetAttribute(petri_kernel,
                         cudaFuncAttributeMaxDynamicSharedMemorySize, SMEM_BYTES);
    petri_kernel<<<BB, NTHREADS, SMEM_BYTES>>>(
        (const float*)d_in[0],  (const float*)d_in[1],  (const float*)d_in[2],
        (const float*)d_in[3],  (const float*)d_in[4],  (const float*)d_in[5],
        (const float*)d_in[6],  (const float*)d_in[7],  (const float*)d_in[8],
        (const float*)d_in[9],  (const float*)d_in[10], (const float*)d_in[11],
        (const float*)d_in[12], (const float*)d_in[13], (const float*)d_in[14],
        (const float*)d_in[15], (float*)d_out);
}

// round 3
// speedup vs baseline: 1.1367x; 1.1367x over previous
#include <cuda_runtime.h>

#define BB 128
#define LL 128
#define TNN 32
#define NTHREADS 512
#define NWARPS 16

typedef unsigned long long ull;

// ---------- packed f32x2 helpers (FFMA2 path: 2 MACs/inst) ----------
__device__ __forceinline__ ull pack2(float x, float y) {
    ull r; asm("mov.b64 %0, {%1,%2};" : "=l"(r) : "f"(x), "f"(y)); return r;
}
__device__ __forceinline__ void unpack2(ull v, float& x, float& y) {
    asm("mov.b64 {%0,%1}, %2;" : "=f"(x), "=f"(y) : "l"(v));
}
__device__ __forceinline__ void fma2(ull& d, ull a, ull b) {
    asm("fma.rn.f32x2 %0, %1, %2, %0;" : "+l"(d) : "l"(a), "l"(b));
}
__device__ __forceinline__ float sel4(float4 v, int kk) {
    return kk == 0 ? v.x : kk == 1 ? v.y : kk == 2 ? v.z : v.w;
}

// ---------- shared memory layout (units: floats) ----------
#define OFF_W1   0        /* 136*128 = 17408 */
#define OFF_W2   17408    /* 128*64  = 8192  */
#define OFF_MARK 25600    /* 129*68  = 8772  */
#define OFF_WB   34372    /* 129*64  = 8256  */
#define OFF_LH   42628    /* 16*4*132 = 8448 : per-warp 4-row leaky(hid) tile */
#define OFF_BASE 51076    /* 128 */
#define OFF_PCB1 51204    /* 128 */
#define OFF_PCB2 51332    /* 64  */
#define OFF_CV   51396    /* 68  */
#define OFF_SC   51464    /* 64  */
#define OFF_PMAX 51528    /* 512 */
#define OFF_PSUM 52040    /* 512 */
#define OFF_SMAX 52552    /* 64  */
#define OFF_BD   52616    /* 640 */
#define OFF_RNZ  53256    /* 129 ints */
#define OFF_TLZ  53385    /* 129 ints */
#define SMEM_FLOATS 53520
#define SMEM_BYTES (SMEM_FLOATS * 4)

// 8-row x 4-col (per lane) K=68 GEMM microkernel, float4-vectorized over k.
// marking rows are 68 floats = 272B = 17*16B -> float4-aligned.
__device__ __forceinline__ void gemm8_k68v(const float* __restrict__ smk,
                                           const int* roff,
                                           const float* __restrict__ wgt,
                                           int h0, ull acc[8][2]) {
#pragma unroll 1
    for (int k4 = 0; k4 < 17; k4++) {
        const int kb = k4 * 4;
        float4 x[8];
#pragma unroll
        for (int q = 0; q < 8; q++)
            x[q] = *(const float4*)(smk + roff[q] + kb);
#pragma unroll
        for (int kk = 0; kk < 4; kk++) {
            float4 w4 = *(const float4*)(wgt + ((kb + kk) << 7) + h0);
            ull w01 = pack2(w4.x, w4.y), w23 = pack2(w4.z, w4.w);
#pragma unroll
            for (int q = 0; q < 8; q++) {
                float xv = sel4(x[q], kk);
                ull xx = pack2(xv, xv);
                fma2(acc[q][0], xx, w01);
                fma2(acc[q][1], xx, w23);
            }
        }
    }
}

__device__ __forceinline__ float leaky(float v) { return v > 0.f ? v : 0.01f * v; }

__global__ __launch_bounds__(NTHREADS, 1)
void petri_kernel(const float* __restrict__ bd,   const float* __restrict__ G,
                  const float* __restrict__ C,    const float* __restrict__ Temb,
                  const float* __restrict__ pcW1, const float* __restrict__ pcb1,
                  const float* __restrict__ pcW2, const float* __restrict__ pcb2,
                  const float* __restrict__ jcW1, const float* __restrict__ jcb1,
                  const float* __restrict__ jfW,  const float* __restrict__ jfb,
                  const float* __restrict__ jtW1, const float* __restrict__ jtb1,
                  const float* __restrict__ jtW2, const float* __restrict__ jtb2,
                  float* __restrict__ out)
{
    extern __shared__ float sm[];
    const int tid  = threadIdx.x;
    const int lane = tid & 31;
    const int w    = tid >> 5;
    const int b    = blockIdx.x;
    const int h0   = lane * 4;

    float* sW1   = sm + OFF_W1;
    float* sW2   = sm + OFF_W2;
    float* sMark = sm + OFF_MARK;
    float* sWB   = sm + OFF_WB;
    float* sLH   = sm + OFF_LH;
    float* sBase = sm + OFF_BASE;
    float* sPcb1 = sm + OFF_PCB1;
    float* sPcb2 = sm + OFF_PCB2;
    float* sCV   = sm + OFF_CV;
    float* sSC   = sm + OFF_SC;
    float* sPMAX = sm + OFF_PMAX;
    float* sPSUM = sm + OFF_PSUM;
    float* sSMAX = sm + OFF_SMAX;
    float* sBD   = sm + OFF_BD;
    int*   rownz = (int*)(sm + OFF_RNZ);
    int*   tailz = (int*)(sm + OFF_TLZ);

    // ---------------- stage weights + init state ----------------
    for (int i = tid; i < (136 * 128) / 4; i += NTHREADS)
        ((float4*)sW1)[i] = ((const float4*)pcW1)[i];
    for (int i = tid; i < (128 * 64) / 4; i += NTHREADS)
        ((float4*)sW2)[i] = ((const float4*)pcW2)[i];
    if (tid < 128) sPcb1[tid] = pcb1[tid];
    else if (tid < 192) sPcb2[tid - 128] = pcb2[tid - 128];
    for (int i = tid; i < 640; i += NTHREADS) sBD[i] = bd[b * 640 + i];
    for (int i = tid; i < 129 * 68; i += NTHREADS) sMark[i] = 0.f;
    if (tid < 129) { rownz[tid] = 0; tailz[tid] = 1; }
    __syncthreads();
    if (tid < 64) sMark[tid] = fmaxf(G[tid], 0.f);
    __syncthreads();
    if (tid == 0) {
        int nz = 0;
        for (int j = 0; j < 68; j++) nz |= (sMark[j] != 0.f);
        rownz[0] = nz;
    }
    __syncthreads();

    float* lhw = sLH + w * (4 * 132);

    // ---------------- sequential scan over L steps ----------------
    for (int i = 0; i < LL; i++) {
        const int a = (int)sBD[i];
        if (a <= 0 || a == TNN + 1) continue;      // inactive: uniform skip
        const float tv0 = sBD[128 + i], tv1 = sBD[256 + i],
                    tv2 = sBD[384 + i], tv3 = sBD[512 + i];
        const int ai = a - 1, gi = a;
        const int nrows = i + 1;

        // Phase A: cond vector, gen row i+1 (safe: rows 0..i untouched)
        if (tid < 64)                      sCV[tid] = fmaxf(C[ai * 64 + tid], 0.f);
        else if (tid < 68)                 sCV[tid] = Temb[ai * 4 + (tid - 64)];
        else if (tid >= 128 && tid < 192)  sMark[(i + 1) * 68 + (tid - 128)] = fmaxf(G[gi * 64 + (tid - 128)], 0.f);
        else if (tid >= 192 && tid < 196) {
            float tv = (tid == 192) ? tv0 : (tid == 193) ? tv1 : (tid == 194) ? tv2 : tv3;
            sMark[(i + 1) * 68 + 64 + (tid - 192)] = tv;
        }
        if (tid == 196) tailz[i + 1] = (tv0 == 0.f && tv1 == 0.f && tv2 == 0.f && tv3 == 0.f);
        __syncthreads();

        // Phase A2: base[h] = pcb1[h] + cond @ pcW1[68:], and rownz[i+1]
        if (tid < 128) {
            float a0 = sPcb1[tid], a1 = 0.f;
#pragma unroll 4
            for (int j = 0; j < 68; j += 2) {
                a0 = fmaf(sCV[j],     sW1[(68 + j) * 128 + tid], a0);
                a1 = fmaf(sCV[j + 1], sW1[(69 + j) * 128 + tid], a1);
            }
            sBase[tid] = a0 + a1;
        }
        if (w == 6) {
            const float* row = sMark + (i + 1) * 68;
            int v = (row[lane] != 0.f) || (row[lane + 32] != 0.f);
            if (lane < 4) v |= (row[64 + lane] != 0.f);
            unsigned nz = __ballot_sync(0xffffffffu, v);
            if (lane == 0) rownz[i + 1] = (nz != 0);
        }
        __syncthreads();

        // Phase B: w = leaky(x@W1 + base) @ W2 + b2, rows 0..i, 8-row warp tiles
        for (int tile = w; tile * 8 < nrows; tile += NWARPS) {
            const int r0 = tile * 8;
            int roff[8];
#pragma unroll
            for (int q = 0; q < 8; q++) roff[q] = min(r0 + q, 128) * 68;

            ull acc[8][2];
            {
                float4 b4 = *(const float4*)(sBase + h0);
                ull b01 = pack2(b4.x, b4.y), b23 = pack2(b4.z, b4.w);
#pragma unroll
                for (int q = 0; q < 8; q++) { acc[q][0] = b01; acc[q][1] = b23; }
            }
            gemm8_k68v(sMark, roff, sW1, h0, acc);

            // GEMM2 in two 4-row passes through the per-warp LH tile
#pragma unroll 1
            for (int pass = 0; pass < 2; pass++) {
#pragma unroll
                for (int q = 0; q < 4; q++) {
                    float a0, a1, a2, a3;
                    unpack2(acc[pass * 4 + q][0], a0, a1);
                    unpack2(acc[pass * 4 + q][1], a2, a3);
                    *(float4*)(lhw + q * 132 + h0) =
                        make_float4(leaky(a0), leaky(a1), leaky(a2), leaky(a3));
                }
                __syncwarp();

                const int g  = lane >> 4;            // half-warp -> 2-row group
                const int n0 = (lane & 15) * 4;      // 4 n-cols per lane
                const float* lha = lhw + (2 * g) * 132;
                const float* lhb = lha + 132;
                ull acc2[2][2];
                {
                    float4 b4 = *(const float4*)(sPcb2 + n0);
                    ull b01 = pack2(b4.x, b4.y), b23 = pack2(b4.z, b4.w);
                    acc2[0][0] = b01; acc2[0][1] = b23;
                    acc2[1][0] = b01; acc2[1][1] = b23;
                }
#pragma unroll 1
                for (int h4 = 0; h4 < 32; h4++) {
                    float4 xa = *(const float4*)(lha + h4 * 4);
                    float4 xb = *(const float4*)(lhb + h4 * 4);
#pragma unroll
                    for (int kk = 0; kk < 4; kk++) {
                        float4 w4 = *(const float4*)(sW2 + (((h4 * 4 + kk)) << 6) + n0);
                        ull w01 = pack2(w4.x, w4.y), w23 = pack2(w4.z, w4.w);
                        float av = sel4(xa, kk), bv = sel4(xb, kk);
                        ull aa = pack2(av, av), bb = pack2(bv, bv);
                        fma2(acc2[0][0], aa, w01); fma2(acc2[0][1], aa, w23);
                        fma2(acc2[1][0], bb, w01); fma2(acc2[1][1], bb, w23);
                    }
                }
#pragma unroll
                for (int j = 0; j < 2; j++) {
                    int r = r0 + pass * 4 + 2 * g + j;
                    if (r < nrows) {
                        float a0, a1, a2, a3;
                        unpack2(acc2[j][0], a0, a1); unpack2(acc2[j][1], a2, a3);
                        *(float4*)(sWB + r * 64 + n0) = make_float4(a0, a1, a2, a3);
                    }
                }
                __syncwarp();
            }
        }
        __syncthreads();

        // Phase C: masked softmax over rows, per column (8 threads/column)
        {
            const int n = tid & 63, c = tid >> 6;
            float m = -1e30f;
            for (int r = c; r < nrows; r += 8) {
                float v = rownz[r] ? sWB[r * 64 + n] : -1e9f;
                m = fmaxf(m, v);
            }
            sPMAX[c * 64 + n] = m;
        }
        __syncthreads();
        if (tid < 64) {
            float m = sPMAX[tid];
#pragma unroll
            for (int c = 1; c < 8; c++) m = fmaxf(m, sPMAX[c * 64 + tid]);
            sSMAX[tid] = m;
        }
        __syncthreads();
        {
            const int n = tid & 63, c = tid >> 6;
            const float mm = sSMAX[n];
            float s = 0.f;
            for (int r = c; r < nrows; r += 8) {
                float v = rownz[r] ? sWB[r * 64 + n] : -1e9f;
                float e = expf(v - mm);
                sWB[r * 64 + n] = e;
                s += e;
            }
            sPSUM[c * 64 + n] = s;
        }
        __syncthreads();
        if (tid < 64) {
            float s = 0.f;
#pragma unroll
            for (int c = 0; c < 8; c++) s += sPSUM[c * 64 + tid];
            sSC[tid] = sCV[tid] / s;      // condC[n] / sum
        }
        __syncthreads();

        // Phase D: marking update + incremental zmask maintenance
        for (int r = w; r < nrows; r += NWARPS) {
            float e0 = sWB[r * 64 + lane];
            float e1 = sWB[r * 64 + lane + 32];
            float v0 = fmaxf(sMark[r * 68 + lane]      - e0 * sSC[lane],      0.f);
            float v1 = fmaxf(sMark[r * 68 + lane + 32] - e1 * sSC[lane + 32], 0.f);
            sMark[r * 68 + lane]      = v0;
            sMark[r * 68 + lane + 32] = v1;
            unsigned nzb = __ballot_sync(0xffffffffu, (v0 != 0.f) || (v1 != 0.f));
            if (lane == 0) rownz[r] = (nzb != 0) || (tailz[r] == 0);
        }
        __syncthreads();
    }

    // ---------------- final scoring phase (reuses W1/W2 regions) ----------------
    float* sJc   = sW1;
    float* sJt   = sW1 + 68 * 128;
    float* spool = sW2;
    float* sjcb  = sW2 + 128;
    float* sjtb  = sW2 + 256;
    float* sjw2  = sW2 + 384;
    float* sjf   = sW2 + 512;
    float* swm   = sW2 + 640;   /* 16 entries */

    __syncthreads();
    if (tid < 128) sjf[tid] = jfW[tid];
    const float jfb_v = jfb[0];
    __syncthreads();

    for (int t = 0; t < TNN; t++) {
        {
            const float4* gjc = (const float4*)(jcW1 + t * 68 * 128);
            const float4* gjt = (const float4*)(jtW1 + t * 68 * 128);
            for (int idx = tid; idx < (68 * 128) / 4; idx += NTHREADS) {
                ((float4*)sJc)[idx] = gjc[idx];
                ((float4*)sJt)[idx] = gjt[idx];
            }
        }
        if (tid < 128) {
            sjcb[tid] = jcb1[t * 128 + tid];
            sjtb[tid] = jtb1[t * 128 + tid];
            sjw2[tid] = jtW2[t * 128 + tid];
            spool[tid] = 0.f;
        }
        __syncthreads();

        // jc path: pooled[h] = sum over nonzero rows of leaky(marking @ jcW1[t] + jcb1[t])
        float pp0 = 0.f, pp1 = 0.f, pp2 = 0.f, pp3 = 0.f;
        for (int tile = w; tile * 8 < 129; tile += NWARPS) {
            const int r0 = tile * 8;
            int roff[8];
#pragma unroll
            for (int q = 0; q < 8; q++) roff[q] = min(r0 + q, 128) * 68;
            ull acc[8][2];
            {
                float4 b4 = *(const float4*)(sjcb + h0);
                ull b01 = pack2(b4.x, b4.y), b23 = pack2(b4.z, b4.w);
#pragma unroll
                for (int q = 0; q < 8; q++) { acc[q][0] = b01; acc[q][1] = b23; }
            }
            gemm8_k68v(sMark, roff, sJc, h0, acc);
#pragma unroll
            for (int q = 0; q < 8; q++) {
                int r = r0 + q;
                if (r < 129 && rownz[r]) {
                    float a0, a1, a2, a3;
                    unpack2(acc[q][0], a0, a1); unpack2(acc[q][1], a2, a3);
                    pp0 += leaky(a0); pp1 += leaky(a1);
                    pp2 += leaky(a2); pp3 += leaky(a3);
                }
            }
        }
        atomicAdd(&spool[h0 + 0], pp0);
        atomicAdd(&spool[h0 + 1], pp1);
        atomicAdd(&spool[h0 + 2], pp2);
        atomicAdd(&spool[h0 + 3], pp3);

        // jt path: tc[r] = leaky(marking @ jtW1[t] + jtb1[t]) . jtW2[t] + jtb2[t]; max over r
        const float w2a = sjw2[h0], w2b = sjw2[h0 + 1], w2c = sjw2[h0 + 2], w2d = sjw2[h0 + 3];
        const float jtb2v = jtb2[t];
        float tmax = -1e30f;
        for (int tile = w; tile * 8 < 129; tile += NWARPS) {
            const int r0 = tile * 8;
            int roff[8];
#pragma unroll
            for (int q = 0; q < 8; q++) roff[q] = min(r0 + q, 128) * 68;
            ull acc[8][2];
            {
                float4 b4 = *(const float4*)(sjtb + h0);
                ull b01 = pack2(b4.x, b4.y), b23 = pack2(b4.z, b4.w);
#pragma unroll
                for (int q = 0; q < 8; q++) { acc[q][0] = b01; acc[q][1] = b23; }
            }
            gemm8_k68v(sMark, roff, sJt, h0, acc);
#pragma unroll
            for (int q = 0; q < 8; q++) {
                float a0, a1, a2, a3;
                unpack2(acc[q][0], a0, a1); unpack2(acc[q][1], a2, a3);
                float d = leaky(a0) * w2a + leaky(a1) * w2b + leaky(a2) * w2c + leaky(a3) * w2d;
                d += __shfl_xor_sync(0xffffffffu, d, 16);
                d += __shfl_xor_sync(0xffffffffu, d, 8);
                d += __shfl_xor_sync(0xffffffffu, d, 4);
                d += __shfl_xor_sync(0xffffffffu, d, 2);
                d += __shfl_xor_sync(0xffffffffu, d, 1);
                if (r0 + q < 129) tmax = fmaxf(tmax, d + jtb2v);
            }
        }
        if (lane == 0) swm[w] = tmax;
        __syncthreads();

        if (w == 0) {
            float pr = spool[lane]      * sjf[lane]
                     + spool[lane + 32] * sjf[lane + 32]
                     + spool[lane + 64] * sjf[lane + 64]
                     + spool[lane + 96] * sjf[lane + 96];
            pr += __shfl_xor_sync(0xffffffffu, pr, 16);
            pr += __shfl_xor_sync(0xffffffffu, pr, 8);
            pr += __shfl_xor_sync(0xffffffffu, pr, 4);
            pr += __shfl_xor_sync(0xffffffffu, pr, 2);
            pr += __shfl_xor_sync(0xffffffffu, pr, 1);
            if (lane == 0) {
                float res = 1.f / (1.f + expf(-(pr + jfb_v)));
                res = fmaxf(res, 1e-5f);
                float tm = swm[0];
#pragma unroll
                for (int j = 1; j < NWARPS; j++) tm = fmaxf(tm, swm[j]);
                out[b * TNN + t] = res * tm - 0.01f * expf(res);
            }
        }
        __syncthreads();
    }
}

extern "C" void kernel_launch(void* const* d_in, const int* in_sizes, int n_in,
                              void* d_out, int out_size) {
    (void)in_sizes; (void)n_in; (void)out_size;
    cudaFuncSetAttribute(petri_kernel,
                         cudaFuncAttributeMaxDynamicSharedMemorySize, SMEM_BYTES);
    petri_kernel<<<BB, NTHREADS, SMEM_BYTES>>>(
        (const float*)d_in[0],  (const float*)d_in[1],  (const float*)d_in[2],
        (const float*)d_in[3],  (const float*)d_in[4],  (const float*)d_in[5],
        (const float*)d_in[6],  (const float*)d_in[7],  (const float*)d_in[8],
        (const float*)d_in[9],  (const float*)d_in[10], (const float*)d_in[11],
        (const float*)d_in[12], (const float*)d_in[13], (const float*)d_in[14],
        (const float*)d_in[15], (float*)d_out);
}